// round 9
// baseline (speedup 1.0000x reference)
#include <cuda_runtime.h>
#include <cuda_bf16.h>
#include <math.h>
#include <stdint.h>

// ContinuousConv1d, all-tensor-core:
//  phase A: xs_p = W(f_p) @ xwin_p  (64x64 circulant x 64x32), HMMA 3-term bf16 split
//  phase B: out[p,o] = bias[o] + sum_j xs[p,j] kernel[o,j], HMMA 3-term, cp.async pipelined
// xs / kernel splits stored in a fixed fragment permutation sigma of j (identical on both
// sides, so the dot product is unchanged).

#define NT1  4096
#define NOC  64
#define NPOS 2048

__device__ uint32_t g_xh[NPOS * 1024];   // bf16x2 words, sigma order
__device__ uint32_t g_xl[NPOS * 1024];
__device__ uint32_t g_kh[NOC * 1024];
__device__ uint32_t g_kl[NOC * 1024];

static __device__ __forceinline__ uint32_t smem_u32(const void* p) {
    uint32_t a;
    asm("{ .reg .u64 t; cvta.to.shared.u64 t, %1; cvt.u32.u64 %0, t; }" : "=r"(a) : "l"(p));
    return a;
}
static __device__ __forceinline__ void ldm4(uint32_t* r, uint32_t addr) {
    asm volatile("ldmatrix.sync.aligned.m8n8.x4.shared.b16 {%0,%1,%2,%3}, [%4];"
                 : "=r"(r[0]), "=r"(r[1]), "=r"(r[2]), "=r"(r[3]) : "r"(addr));
}
static __device__ __forceinline__ void ldm4t(uint32_t* r, uint32_t addr) {
    asm volatile("ldmatrix.sync.aligned.m8n8.x4.trans.shared.b16 {%0,%1,%2,%3}, [%4];"
                 : "=r"(r[0]), "=r"(r[1]), "=r"(r[2]), "=r"(r[3]) : "r"(addr));
}
static __device__ __forceinline__ void mma_bf16(float* d, const uint32_t* a,
                                                uint32_t b0, uint32_t b1) {
    asm volatile("mma.sync.aligned.m16n8k16.row.col.f32.bf16.bf16.f32 "
                 "{%0,%1,%2,%3}, {%4,%5,%6,%7}, {%8,%9}, {%0,%1,%2,%3};"
                 : "+f"(d[0]), "+f"(d[1]), "+f"(d[2]), "+f"(d[3])
                 : "r"(a[0]), "r"(a[1]), "r"(a[2]), "r"(a[3]), "r"(b0), "r"(b1));
}
static __device__ __forceinline__ void split2(float a, float b, uint32_t& hw, uint32_t& lw) {
    __nv_bfloat162 h2 = __floats2bfloat162_rn(a, b);
    float ra = a - __bfloat162float(h2.x);
    float rb = b - __bfloat162float(h2.y);
    __nv_bfloat162 l2 = __floats2bfloat162_rn(ra, rb);
    hw = *reinterpret_cast<uint32_t*>(&h2);
    lw = *reinterpret_cast<uint32_t*>(&l2);
}
static __device__ __forceinline__ void cpasync16(uint32_t dst, const void* src) {
    asm volatile("cp.async.cg.shared.global [%0], [%1], 16;" :: "r"(dst), "l"(src));
}

// ---------------- Phase A smem layout (bytes) ----------------
#define SA_X   0
#define SA_W   20480
#define SA_TR  53248
#define SA_TP  53760
#define SA_TOT 54272

__global__ __launch_bounds__(256, 3)
void cc1d_phaseA(const float* __restrict__ x, const float* __restrict__ idxg,
                 const float* __restrict__ kern, const float* __restrict__ bias,
                 float* __restrict__ out) {
    extern __shared__ char sm[];
    const int t = threadIdx.x;
    const int wid = t >> 5, lane = t & 31;

    // ---------- tail CTAs: write kernel splits in sigma order ----------
    if (blockIdx.x >= 1024) {
        int wb = blockIdx.x - 1024;         // 0..31
        #pragma unroll
        for (int rr = 0; rr < 2; ++rr) {
            int o = wb * 2 + rr;
            #pragma unroll
            for (int i = 0; i < 4; ++i) {
                int W = t + i * 256;        // word 0..1023
                int mh = W >> 9, T = (W >> 6) & 7, r = (W >> 5) & 1, L = W & 31;
                int tm = T >> 2, tn = T & 3, q = L >> 2, id = L & 3;
                int m = mh * 32 + tm * 16 + r * 8 + q;
                int c = tn * 8 + id * 2;
                int j0 = c * 64 + m;
                uint32_t hw, lw;
                split2(kern[o * 2048 + j0], kern[o * 2048 + j0 + 64], hw, lw);
                g_kh[o * 1024 + W] = hw;
                g_kl[o * 1024 + W] = lw;
            }
        }
        return;
    }

    const int pos0 = blockIdx.x * 2;
    const int b = pos0 >> 9;

    // init out = bias (phase B accumulates atomically on top)
    if (blockIdx.x < 512) out[blockIdx.x * 256 + t] = bias[t & 63];

    float iv[2]; int ibase[2];
    #pragma unroll
    for (int s = 0; s < 2; ++s) { iv[s] = idxg[pos0 + s]; ibase[s] = (int)floorf(iv[s]); }

    // ---------- load windows, split to bf16 hi/lo, store [k][c] pitch-80 ----------
    #pragma unroll
    for (int i = 0; i < 4; ++i) {
        int u  = t + i * 256;               // 0..1023
        int p  = u >> 9;
        int s2 = u & 511;
        int k  = s2 >> 3, c4 = s2 & 7;
        int t1 = ibase[p] + k - 32;
        float4 v = make_float4(0.f, 0.f, 0.f, 0.f);
        if (t1 >= 0 && t1 < NT1)
            v = reinterpret_cast<const float4*>(x)[(b * NT1 + t1) * 8 + c4];
        uint32_t hw0, lw0, hw1, lw1;
        split2(v.x, v.y, hw0, lw0);
        split2(v.z, v.w, hw1, lw1);
        char* base = sm + SA_X + p * 10240 + k * 80 + c4 * 8;
        reinterpret_cast<uint32_t*>(base)[0] = hw0;
        reinterpret_cast<uint32_t*>(base)[1] = hw1;
        reinterpret_cast<uint32_t*>(base + 5120)[0] = lw0;
        reinterpret_cast<uint32_t*>(base + 5120)[1] = lw1;
    }
    // ---------- taps (Dirichlet), bf16 hi/lo (fast-math sin/cos; bf16 absorbs error) ----------
    if (t < 128) {
        int p = t >> 6, j = t & 63;
        float f  = iv[p] - floorf(iv[p]);
        float u  = f + (float)j;
        float a  = u * 0.098174770424681038f;   // pi/32
        float s2 = __sinf(0.5f * a);
        float wv;
        if (fabsf(s2) < 1e-5f) wv = 1.f;
        else wv = (1.f + 2.f * __sinf(15.5f * a) * __cosf(16.f * a) / s2 + __cosf(32.f * a)) * (1.f / 64.f);
        __nv_bfloat16 hv = __float2bfloat16_rn(wv);
        __nv_bfloat16 lv = __float2bfloat16_rn(wv - __bfloat162float(hv));
        reinterpret_cast<uint16_t*>(sm + SA_TR + p * 256)[j]       = *reinterpret_cast<uint16_t*>(&hv);
        reinterpret_cast<uint16_t*>(sm + SA_TR + p * 256 + 128)[j] = *reinterpret_cast<uint16_t*>(&lv);
    }
    __syncthreads();

    // ---------- odd-offset packed tap tables ----------
    if (t < 64) {
        int p = t >> 5, w = t & 31;
        const uint16_t* rh = reinterpret_cast<const uint16_t*>(sm + SA_TR + p * 256);
        const uint16_t* rl = rh + 64;
        uint32_t ph = (uint32_t)rh[2 * w + 1] | ((uint32_t)rh[(2 * w + 2) & 63] << 16);
        uint32_t pl = (uint32_t)rl[2 * w + 1] | ((uint32_t)rl[(2 * w + 2) & 63] << 16);
        reinterpret_cast<uint32_t*>(sm + SA_TP + p * 256)[w]       = ph;
        reinterpret_cast<uint32_t*>(sm + SA_TP + p * 256 + 128)[w] = pl;
    }
    __syncthreads();

    const int p  = wid >> 2;                // warp position
    const int mh = (wid >> 1) & 1;          // m half (32 rows)
    const int ch = wid & 1;                 // c half (16 cols)

    // ---------- build W rows m = mh*32 + ch*16 .. +15 ----------
    {
        const uint32_t* rawH = reinterpret_cast<const uint32_t*>(sm + SA_TR + p * 256);
        const uint32_t* rawL = reinterpret_cast<const uint32_t*>(sm + SA_TR + p * 256 + 128);
        const uint32_t* p1H  = reinterpret_cast<const uint32_t*>(sm + SA_TP + p * 256);
        const uint32_t* p1L  = reinterpret_cast<const uint32_t*>(sm + SA_TP + p * 256 + 128);
        char* wtH = sm + SA_W + p * 16384;
        char* wtL = wtH + 8192;
        #pragma unroll 4
        for (int rr = 0; rr < 16; ++rr) {
            int m = mh * 32 + ch * 16 + rr;
            uint32_t wh, wl;
            if (m & 1) {
                int u = (lane - ((m + 1) >> 1)) & 31;
                wh = p1H[u]; wl = p1L[u];
            } else {
                int u = (lane - (m >> 1)) & 31;
                wh = rawH[u]; wl = rawL[u];
            }
            uint32_t off = (uint32_t)m * 128u + (uint32_t)(((lane >> 2) ^ (m & 7)) << 4)
                         + (uint32_t)((lane & 3) << 2);
            *reinterpret_cast<uint32_t*>(wtH + off) = wh;
            *reinterpret_cast<uint32_t*>(wtL + off) = wl;
        }
    }
    __syncthreads();

    // ---------- MMA: warp computes xs rows mh*32..+31, cols ch*16..+15 ----------
    const uint32_t sb = smem_u32(sm);
    const uint32_t aHb = sb + SA_W + p * 16384;
    const uint32_t aLb = aHb + 8192;
    const uint32_t xHb = sb + SA_X + p * 10240;
    const uint32_t xLb = xHb + 5120;
    const int arow0 = mh * 32 + (lane & 15);
    const int aKU   = lane >> 4;
    const int bg = lane >> 3, bi = lane & 7;
    const int bkOff = (bg & 1) * 8 + bi;
    const int bnCol = ch * 16 + (bg >> 1) * 8;

    float acc[2][2][4];
    #pragma unroll
    for (int tm = 0; tm < 2; ++tm)
        #pragma unroll
        for (int tn = 0; tn < 2; ++tn)
            #pragma unroll
            for (int q = 0; q < 4; ++q) acc[tm][tn][q] = 0.f;

    #pragma unroll
    for (int s = 0; s < 4; ++s) {
        uint32_t ah[2][4], al[2][4];
        #pragma unroll
        for (int tm = 0; tm < 2; ++tm) {
            int ar = arow0 + tm * 16;
            uint32_t sw = (uint32_t)(((2 * s + aKU) ^ (ar & 7)) << 4);
            ldm4(ah[tm], aHb + (uint32_t)ar * 128u + sw);
            ldm4(al[tm], aLb + (uint32_t)ar * 128u + sw);
        }
        uint32_t bh[4], bl[4];
        uint32_t baddr = (uint32_t)(s * 16 + bkOff) * 80u + (uint32_t)bnCol * 2u;
        ldm4t(bh, xHb + baddr);
        ldm4t(bl, xLb + baddr);
        #pragma unroll
        for (int tm = 0; tm < 2; ++tm)
            #pragma unroll
            for (int tn = 0; tn < 2; ++tn) {
                mma_bf16(acc[tm][tn], ah[tm], bh[2 * tn], bh[2 * tn + 1]);
                mma_bf16(acc[tm][tn], al[tm], bh[2 * tn], bh[2 * tn + 1]);
                mma_bf16(acc[tm][tn], ah[tm], bl[2 * tn], bl[2 * tn + 1]);
            }
    }

    // ---------- epilogue: sigma-order store (coalesced) ----------
    uint32_t* oh = g_xh + (pos0 + p) * 1024 + mh * 512;
    uint32_t* ol = g_xl + (pos0 + p) * 1024 + mh * 512;
    #pragma unroll
    for (int tm = 0; tm < 2; ++tm)
        #pragma unroll
        for (int tn = 0; tn < 2; ++tn) {
            int T = tm * 4 + ch * 2 + tn;
            #pragma unroll
            for (int r = 0; r < 2; ++r) {
                uint32_t hw, lw;
                split2(acc[tm][tn][2 * r], acc[tm][tn][2 * r + 1], hw, lw);
                oh[T * 64 + r * 32 + lane] = hw;
                ol[T * 64 + r * 32 + lane] = lw;
            }
        }
}

// ---------------- Phase B: out += xs @ kernel^T (sigma order), cp.async pipeline ----------------
// grid = 32 m-tiles x 16 k-splits. Per CTA: 64 words of K, 2 chunks of 32, fully prefetched.
#define KSPL 16
#define SB_TOT 65536

__global__ __launch_bounds__(256, 3)
void cc1d_phaseB(float* __restrict__ out) {
    extern __shared__ char sm[];
    const uint32_t sb = smem_u32(sm);
    const int t = threadIdx.x, wid = t >> 5, lane = t & 31;
    const int mt = blockIdx.x >> 4;
    const int ks = blockIdx.x & 15;
    const int p0 = mt * 64;

    const int mtile = wid >> 1;
    const int nh    = wid & 1;
    const int arow  = mtile * 16 + (lane & 15);
    const int aKU   = lane >> 4;
    const int nIdx  = (lane & 7) + ((lane >> 4) << 3);
    const int bKU   = (lane >> 3) & 1;

    const uint32_t* gsrc[4] = {g_xh, g_xl, g_kh, g_kl};

    #define STAGE(CH, BUF) do {                                                    \
        int wb0_ = ks * 64 + (CH) * 32;                                            \
        uint32_t bbase_ = (uint32_t)(BUF) * 32768u;                                \
        _Pragma("unroll")                                                          \
        for (int i_ = 0; i_ < 8; ++i_) {                                           \
            int u_   = t + i_ * 256;                                               \
            int arr_ = u_ >> 9;                                                    \
            int rem_ = u_ & 511;                                                   \
            int row_ = rem_ >> 3;                                                  \
            int un_  = rem_ & 7;                                                   \
            int srow_ = (arr_ < 2) ? (p0 + row_) : row_;                           \
            const uint32_t* sp_ = gsrc[arr_] + (size_t)srow_ * 1024 + wb0_ + un_ * 4; \
            uint32_t d_ = sb + bbase_ + (uint32_t)arr_ * 8192u                     \
                        + (uint32_t)row_ * 128u + (uint32_t)((un_ ^ (row_ & 7)) << 4); \
            cpasync16(d_, sp_);                                                    \
        }                                                                          \
    } while (0)

    float acc[4][4];
    #pragma unroll
    for (int tn = 0; tn < 4; ++tn)
        #pragma unroll
        for (int q = 0; q < 4; ++q) acc[tn][q] = 0.f;

    STAGE(0, 0);
    asm volatile("cp.async.commit_group;" ::: "memory");
    STAGE(1, 1);
    asm volatile("cp.async.commit_group;" ::: "memory");

    #pragma unroll
    for (int c = 0; c < 2; ++c) {
        if (c == 0) asm volatile("cp.async.wait_group 1;" ::: "memory");
        else        asm volatile("cp.async.wait_group 0;" ::: "memory");
        __syncthreads();

        const uint32_t bbase = sb + (uint32_t)c * 32768u;
        #pragma unroll
        for (int s = 0; s < 4; ++s) {
            uint32_t ah[4], al[4];
            {
                uint32_t sw = (uint32_t)(((2 * s + aKU) ^ (arow & 7)) << 4);
                ldm4(ah, bbase + (uint32_t)arow * 128u + sw);
                ldm4(al, bbase + 8192u + (uint32_t)arow * 128u + sw);
            }
            uint32_t bh[2][4], bl[2][4];
            #pragma unroll
            for (int g = 0; g < 2; ++g) {
                int nr = nh * 32 + g * 16 + nIdx;
                uint32_t sw = (uint32_t)(((2 * s + bKU) ^ (nr & 7)) << 4);
                ldm4(bh[g], bbase + 16384u + (uint32_t)nr * 128u + sw);
                ldm4(bl[g], bbase + 24576u + (uint32_t)nr * 128u + sw);
            }
            #pragma unroll
            for (int tn = 0; tn < 4; ++tn) {
                int g = tn >> 1, q0 = (tn & 1) * 2;
                mma_bf16(acc[tn], ah, bh[g][q0], bh[g][q0 + 1]);
                mma_bf16(acc[tn], al, bh[g][q0], bh[g][q0 + 1]);
                mma_bf16(acc[tn], ah, bl[g][q0], bl[g][q0 + 1]);
            }
        }
    }

    // ---------- epilogue: atomic accumulate (bias already in out) ----------
    const int quad = lane >> 2, id = lane & 3;
    const int r0 = p0 + mtile * 16 + quad;
    #pragma unroll
    for (int tn = 0; tn < 4; ++tn) {
        int c0 = nh * 32 + tn * 8 + id * 2;
        atomicAdd(&out[r0 * NOC + c0],           acc[tn][0]);
        atomicAdd(&out[r0 * NOC + c0 + 1],       acc[tn][1]);
        atomicAdd(&out[(r0 + 8) * NOC + c0],     acc[tn][2]);
        atomicAdd(&out[(r0 + 8) * NOC + c0 + 1], acc[tn][3]);
    }
    #undef STAGE
}

extern "C" void kernel_launch(void* const* d_in, const int* in_sizes, int n_in,
                              void* d_out, int out_size)
{
    const float* x    = (const float*)d_in[0];
    const float* idx  = (const float*)d_in[1];
    const float* kern = (const float*)d_in[2];
    const float* bias = (const float*)d_in[3];
    float* out = (float*)d_out;
    (void)in_sizes; (void)n_in; (void)out_size;

    cudaFuncSetAttribute(cc1d_phaseA, cudaFuncAttributeMaxDynamicSharedMemorySize, SA_TOT);
    cc1d_phaseA<<<1024 + 32, 256, SA_TOT>>>(x, idx, kern, bias, out);

    cudaFuncSetAttribute(cc1d_phaseB, cudaFuncAttributeMaxDynamicSharedMemorySize, SB_TOT);
    cc1d_phaseB<<<32 * KSPL, 256, SB_TOT>>>(out);
}